// round 4
// baseline (speedup 1.0000x reference)
#include <cuda_runtime.h>
#include <cooperative_groups.h>

namespace cg = cooperative_groups;

#define BATCH     8
#define NPTS      32768
#define CIN_DIM   128
#define MS        (NPTS / 4)          // 8192 samples
#define CLUSTER_X 8                   // CTAs per batch (one CGA cluster)
#define NTHREADS  256
#define PPT       (NPTS / (CLUSTER_X * NTHREADS))   // 16 points per thread
#define NWARPS    (NTHREADS / 32)

// scratch for sampled indices (device global: no allocation allowed)
__device__ int g_sample_idx[BATCH * MS];

struct __align__(32) Slot {
    float v;
    int   i;
    float x, y, z;
    int   pad0, pad1, pad2;
};

__global__ void __cluster_dims__(CLUSTER_X, 1, 1) __launch_bounds__(NTHREADS, 1)
fps_kernel(const float* __restrict__ xyz)
{
    cg::cluster_group cluster = cg::this_cluster();
    const int rank  = (int)cluster.block_rank();
    const int batch = blockIdx.x / CLUSTER_X;
    const int tid   = threadIdx.x;
    const int warp  = tid >> 5;
    const int lane  = tid & 31;

    __shared__ Slot  slots[2][CLUSTER_X];   // double-buffered by iteration parity
    __shared__ Slot  warp_part[NWARPS];
    __shared__ float bc_x, bc_y, bc_z;
    __shared__ int   bc_i;

    const float* sx = xyz + (size_t)batch * 3 * NPTS;
    const float* sy = sx + NPTS;
    const float* sz = sy + NPTS;

    const int base = rank * (NTHREADS * PPT) + tid;

    // register-resident point data + running min distance
    float px[PPT], py[PPT], pz[PPT], dst[PPT];
#pragma unroll
    for (int k = 0; k < PPT; k++) {
        const int g = base + k * NTHREADS;
        px[k]  = sx[g];
        py[k]  = sy[g];
        pz[k]  = sz[g];
        dst[k] = 1e10f;
    }

    // initial farthest = point 0 (matches reference's deterministic seed)
    float cx = sx[0], cy = sy[0], cz = sz[0];
    int   fi = 0;

    for (int t = 0; t < MS; t++) {
        if (rank == 0 && tid == 0)
            g_sample_idx[batch * MS + t] = fi;

        // ---- per-thread: update distances, track local argmax (first-max tiebreak) ----
        float bv = -1.0f;
        int   bi = 0x7fffffff;
        float bxx = 0.f, byy = 0.f, bzz = 0.f;
#pragma unroll
        for (int k = 0; k < PPT; k++) {
            // LHS-preferred FMA fusion of the tree form:
            //   d = fma(dz,dz, fma(dx,dx, dy*dy))
            const float dx = __fadd_rn(px[k], -cx);
            const float dy = __fadd_rn(py[k], -cy);
            const float dz = __fadd_rn(pz[k], -cz);
            const float d  = __fmaf_rn(dz, dz,
                             __fmaf_rn(dx, dx,
                             __fmul_rn(dy, dy)));
            const float nd = fminf(dst[k], d);
            dst[k] = nd;
            if (nd > bv) {          // strict > keeps the earliest (lowest) index
                bv  = nd;
                bi  = base + k * NTHREADS;
                bxx = px[k]; byy = py[k]; bzz = pz[k];
            }
        }

        // ---- warp argmax reduce (carry winner coords) ----
#pragma unroll
        for (int off = 16; off > 0; off >>= 1) {
            const float ov = __shfl_down_sync(0xffffffffu, bv,  off);
            const int   oi = __shfl_down_sync(0xffffffffu, bi,  off);
            const float ox = __shfl_down_sync(0xffffffffu, bxx, off);
            const float oy = __shfl_down_sync(0xffffffffu, byy, off);
            const float oz = __shfl_down_sync(0xffffffffu, bzz, off);
            if (ov > bv || (ov == bv && oi < bi)) {
                bv = ov; bi = oi; bxx = ox; byy = oy; bzz = oz;
            }
        }
        if (lane == 0) {
            warp_part[warp].v = bv;  warp_part[warp].i = bi;
            warp_part[warp].x = bxx; warp_part[warp].y = byy; warp_part[warp].z = bzz;
        }
        __syncthreads();

        const int par = t & 1;

        // ---- block argmax reduce (warp 0), write this CTA's slot ----
        if (warp == 0) {
            float wv; int wi; float wx, wy, wz;
            if (lane < NWARPS) {
                wv = warp_part[lane].v; wi = warp_part[lane].i;
                wx = warp_part[lane].x; wy = warp_part[lane].y; wz = warp_part[lane].z;
            } else {
                wv = -2.0f; wi = 0x7fffffff; wx = wy = wz = 0.f;
            }
#pragma unroll
            for (int off = 4; off > 0; off >>= 1) {
                const float ov = __shfl_down_sync(0xffffffffu, wv, off);
                const int   oi = __shfl_down_sync(0xffffffffu, wi, off);
                const float ox = __shfl_down_sync(0xffffffffu, wx, off);
                const float oy = __shfl_down_sync(0xffffffffu, wy, off);
                const float oz = __shfl_down_sync(0xffffffffu, wz, off);
                if (ov > wv || (ov == wv && oi < wi)) {
                    wv = ov; wi = oi; wx = ox; wy = oy; wz = oz;
                }
            }
            if (lane == 0) {
                slots[par][rank].v = wv;  slots[par][rank].i = wi;
                slots[par][rank].x = wx;  slots[par][rank].y = wy;  slots[par][rank].z = wz;
            }
        }

        // one cluster barrier per iteration (parity double-buffer handles WAR)
        cluster.sync();

        // ---- cluster argmax: lane r reads rank r's slot via DSMEM ----
        if (warp == 0) {
            float wv; int wi; float wx, wy, wz;
            if (lane < CLUSTER_X) {
                const Slot* p = (const Slot*)cluster.map_shared_rank(
                    (void*)&slots[par][lane], lane);
                wv = p->v; wi = p->i; wx = p->x; wy = p->y; wz = p->z;
            } else {
                wv = -2.0f; wi = 0x7fffffff; wx = wy = wz = 0.f;
            }
#pragma unroll
            for (int off = 4; off > 0; off >>= 1) {
                const float ov = __shfl_down_sync(0xffffffffu, wv, off);
                const int   oi = __shfl_down_sync(0xffffffffu, wi, off);
                const float ox = __shfl_down_sync(0xffffffffu, wx, off);
                const float oy = __shfl_down_sync(0xffffffffu, wy, off);
                const float oz = __shfl_down_sync(0xffffffffu, wz, off);
                if (ov > wv || (ov == wv && oi < wi)) {
                    wv = ov; wi = oi; wx = ox; wy = oy; wz = oz;
                }
            }
            if (lane == 0) {
                bc_i = wi; bc_x = wx; bc_y = wy; bc_z = wz;
            }
        }
        __syncthreads();

        fi = bc_i; cx = bc_x; cy = bc_y; cz = bc_z;
    }
}

// Gather epilogue: out = [xyz_sampled (B,3,M) | feature_sampled (B,CIN,M)]
__global__ void gather_kernel(const float* __restrict__ xyz,
                              const float* __restrict__ feat,
                              float* __restrict__ out)
{
    const int m = blockIdx.x * blockDim.x + threadIdx.x;   // 0..MS-1
    const int b = blockIdx.y;
    if (m >= MS) return;

    const int i = g_sample_idx[b * MS + m];

    const float* sxyz = xyz + (size_t)b * 3 * NPTS;
    float*       oxyz = out + (size_t)b * 3 * MS;
#pragma unroll
    for (int c = 0; c < 3; c++)
        oxyz[(size_t)c * MS + m] = sxyz[(size_t)c * NPTS + i];

    const float* sf = feat + (size_t)b * CIN_DIM * NPTS;
    float*       of = out + (size_t)BATCH * 3 * MS + (size_t)b * CIN_DIM * MS;
#pragma unroll 8
    for (int c = 0; c < CIN_DIM; c++)
        of[(size_t)c * MS + m] = sf[(size_t)c * NPTS + i];
}

extern "C" void kernel_launch(void* const* d_in, const int* in_sizes, int n_in,
                              void* d_out, int out_size)
{
    const float* xyz  = (const float*)d_in[0];   // [B,3,N] fp32
    const float* feat = (const float*)d_in[1];   // [B,CIN,N] fp32
    float*       out  = (float*)d_out;

    fps_kernel<<<BATCH * CLUSTER_X, NTHREADS>>>(xyz);

    dim3 grid((MS + 255) / 256, BATCH);
    gather_kernel<<<grid, 256>>>(xyz, feat, out);
}